// round 12
// baseline (speedup 1.0000x reference)
#include <cuda_runtime.h>
#include <cuda_bf16.h>
#include <cuda_fp16.h>
#include <cstdint>

typedef unsigned long long ull;

#define NB 16
#define NC 64
#define NN 2048
#define MT 128              // node tile per CTA
#define KC 32               // K chunk
#define NCHUNK (NN / KC)
#define TILEB 4096          // P tile: 4KB fp16 hi only
#define TILEA 16384         // split adj tile: 8KB hi + 8KB lo

// stage layout (bytes): AHI 0..8K, ALO 8..16K, PHI 16..20K
#define STG_STRIDE 20480
#define OFF_ALO 8192
#define OFF_PHI 16384

__device__ float g_Z[(size_t)3 * NB * NC * NN];                           // Z0..Z2 fp32
__device__ __align__(16) unsigned char g_ZS[(size_t)NB * NCHUNK * TILEB]; // Z3 fp16
__device__ __align__(16) unsigned char g_S0[(size_t)NB * NCHUNK * TILEB]; // P after step0
__device__ __align__(16) unsigned char g_S1[(size_t)NB * NCHUNK * TILEB]; // P after step1
__device__ __align__(16) unsigned char g_AS[(size_t)NB * 16 * NCHUNK * TILEA]; // split adj

// ---------------------------------------------------------------- helpers ---
__device__ __forceinline__ uint32_t smem_u32(const void* p) {
    uint32_t a;
    asm("{ .reg .u64 t; cvta.to.shared.u64 t, %1; cvt.u32.u64 %0, t; }"
        : "=r"(a) : "l"(p));
    return a;
}
__device__ __forceinline__ void sts128(uint32_t a, uint32_t v0, uint32_t v1,
                                       uint32_t v2, uint32_t v3) {
    asm volatile("st.shared.v4.b32 [%0], {%1, %2, %3, %4};"
                 :: "r"(a), "r"(v0), "r"(v1), "r"(v2), "r"(v3) : "memory");
}
__device__ __forceinline__ uint4 lds128(uint32_t a) {
    uint4 v;
    asm volatile("ld.shared.v4.b32 {%0,%1,%2,%3}, [%4];"
                 : "=r"(v.x), "=r"(v.y), "=r"(v.z), "=r"(v.w) : "r"(a));
    return v;
}
__device__ __forceinline__ void ldsm4(uint32_t* r, uint32_t addr) {
    asm volatile("ldmatrix.sync.aligned.m8n8.x4.shared.b16 {%0,%1,%2,%3}, [%4];"
                 : "=r"(r[0]), "=r"(r[1]), "=r"(r[2]), "=r"(r[3]) : "r"(addr));
}
// fp16 MMA, fp32 accumulate
__device__ __forceinline__ void mma16816(float* d, const uint32_t* a,
                                         uint32_t b0, uint32_t b1) {
    asm volatile(
        "mma.sync.aligned.m16n8k16.row.col.f32.f16.f16.f32 "
        "{%0,%1,%2,%3}, {%4,%5,%6,%7}, {%8,%9}, {%0,%1,%2,%3};"
        : "+f"(d[0]), "+f"(d[1]), "+f"(d[2]), "+f"(d[3])
        : "r"(a[0]), "r"(a[1]), "r"(a[2]), "r"(a[3]), "r"(b0), "r"(b1));
}
// fp16 hi/lo split of a float pair
__device__ __forceinline__ void splitpairh(float x, float y, uint32_t& hi, uint32_t& lo) {
    __half2 h = __floats2half2_rn(x, y);
    float2 hf = __half22float2(h);
    __half2 l = __floats2half2_rn(x - hf.x, y - hf.y);
    hi = *reinterpret_cast<uint32_t*>(&h);
    lo = *reinterpret_cast<uint32_t*>(&l);
}
__device__ __forceinline__ uint32_t packh(float x, float y) {
    __half2 h = __floats2half2_rn(x, y);
    return *reinterpret_cast<uint32_t*>(&h);
}
__device__ __forceinline__ void cpasync16(uint32_t dst, const void* src) {
    asm volatile("cp.async.cg.shared.global [%0], [%1], 16;"
                 :: "r"(dst), "l"(src) : "memory");
}
#define CP_COMMIT() asm volatile("cp.async.commit_group;" ::: "memory")
#define CP_WAIT0()  asm volatile("cp.async.wait_group 0;" ::: "memory")
#define CP_WAIT2()  asm volatile("cp.async.wait_group 2;" ::: "memory")

// ----------------------------------------------------------------- FFMA2 ----
__device__ __forceinline__ ull pack2(float lo, float hi) {
    ull r; asm("mov.b64 %0, {%1, %2};" : "=l"(r) : "f"(lo), "f"(hi)); return r;
}
__device__ __forceinline__ void unpack2(ull v, float& lo, float& hi) {
    asm("mov.b64 {%0, %1}, %2;" : "=f"(lo), "=f"(hi) : "l"(v));
}
__device__ __forceinline__ void fma2(ull& d, ull a, ull b) {
    asm("fma.rn.f32x2 %0, %1, %2, %0;" : "+l"(d) : "l"(a), "l"(b));
}

// ---------------------------------------------------------------------------
// Projection: Z_d[b][c][m] = sum_k U_d[c][k] * x[b][k][m]
// d<3: fp32 to g_Z. d==3: fp16 swizzled tiles to g_ZS.
// ---------------------------------------------------------------------------
__global__ __launch_bounds__(256) void proj_kernel(
    const float* __restrict__ x, const float* __restrict__ W1,
    const float* __restrict__ W2)
{
    __shared__ float Ut[64][68];
    __shared__ float xs[64][128];
    const int d = blockIdx.z, b = blockIdx.y, m0 = blockIdx.x * 128;
    const int tid = threadIdx.x;

    for (int i = tid; i < 64 * 64; i += 256) {
        int c = i >> 6, k = i & 63;
        Ut[k][c] = (c < 32) ? W1[(d * 32 + c) * 64 + k]
                            : W2[(d * 32 + (c - 32)) * 64 + k];
    }
    for (int i = tid; i < 64 * 32; i += 256) {
        int k = i >> 5, j4 = (i & 31) * 4;
        *(float4*)&xs[k][j4] = *(const float4*)&x[((size_t)b * NC + k) * NN + m0 + j4];
    }
    __syncthreads();

    const int cg = (tid >> 5) * 8;
    const int mg = (tid & 31) * 4;
    ull acc[8][2];
#pragma unroll
    for (int c = 0; c < 8; c++) { acc[c][0] = 0ull; acc[c][1] = 0ull; }

#pragma unroll 8
    for (int k = 0; k < 64; k++) {
        float4 bv = *(const float4*)&xs[k][mg];
        ull b01 = pack2(bv.x, bv.y), b23 = pack2(bv.z, bv.w);
        float4 a0 = *(const float4*)&Ut[k][cg];
        float4 a1 = *(const float4*)&Ut[k][cg + 4];
        float av[8] = {a0.x, a0.y, a0.z, a0.w, a1.x, a1.y, a1.z, a1.w};
#pragma unroll
        for (int c = 0; c < 8; c++) {
            ull a2 = pack2(av[c], av[c]);
            fma2(acc[c][0], a2, b01);
            fma2(acc[c][1], a2, b23);
        }
    }
    if (d < 3) {
        const size_t base = ((size_t)d * NB + b) * NC * (size_t)NN;
#pragma unroll
        for (int c = 0; c < 8; c++) {
            float4 o;
            unpack2(acc[c][0], o.x, o.y);
            unpack2(acc[c][1], o.z, o.w);
            *(float4*)&g_Z[base + (size_t)(cg + c) * NN + m0 + mg] = o;
        }
    } else {
        const int gm = m0 + mg;
        const int kc = gm >> 5, kk = gm & 31;
        unsigned char* tile = g_ZS + ((size_t)(b * NCHUNK + kc)) * TILEB;
#pragma unroll
        for (int c = 0; c < 8; c++) {
            float4 o;
            unpack2(acc[c][0], o.x, o.y);
            unpack2(acc[c][1], o.z, o.w);
            const int cc = cg + c;
            const uint32_t xorc = (uint32_t)((cc << 3) & 0x30);
            const uint32_t rowo = (uint32_t)cc * 64;
            uint32_t off = rowo + (((uint32_t)(kk * 2)) ^ xorc);
            *(uint32_t*)(tile + off) = packh(o.x, o.y);
            off = rowo + (((uint32_t)((kk + 2) * 2)) ^ xorc);
            *(uint32_t*)(tile + off) = packh(o.z, o.w);
        }
    }
}

// ---------------------------------------------------------------------------
// Step 0: adj fp32 LDG -> fp16 hi/lo split -> STS; P (fp16) via cp.async.
// Dumps split-adj tiles to g_AS for steps 1/2. 2 MMA products.
// ---------------------------------------------------------------------------
__global__ void __launch_bounds__(256, 2) first_step_kernel(
    const float* __restrict__ adj)
{
    const unsigned char* Psrc = g_ZS;
    unsigned char* Pdst = g_S0;
    const float* Zad = g_Z + (size_t)2 * NB * NC * NN;   // Z2

    extern __shared__ char dynsm[];
    const uint32_t sbase = (smem_u32(dynsm) + 1023u) & ~1023u;

    const int tid = threadIdx.x, warp = tid >> 5, lane = tid & 31;
    const int b = blockIdx.y, mt0 = blockIdx.x, m0 = mt0 * MT;
    const float* Jm = adj + (size_t)b * NN * NN + m0;
    const unsigned char* Pb = Psrc + (size_t)b * NCHUNK * TILEB;
    unsigned char* Adump = g_AS + ((size_t)(b * 16 + mt0)) * NCHUNK * TILEA;

    const int amld = tid & 127;
    const int akb  = (tid >> 7) * 16;
    const float* aptr = Jm + (size_t)akb * NN + amld;
    const uint32_t axor = (uint32_t)((amld << 3) & 0x30);
    const uint32_t relA0 = (uint32_t)(amld * 64) + (((uint32_t)(akb * 2)) ^ axor);
    const uint32_t relA1 = (uint32_t)(amld * 64) + (((uint32_t)(akb * 2 + 16)) ^ axor);

    const int cb = (warp >> 2) * 32;
    const int nb = (warp & 3) * 32;
    const int lrow = lane & 15;
    const uint32_t lkb = (uint32_t)((lane >> 4) * 16);

    float acc[2][4][4];
#pragma unroll
    for (int mt = 0; mt < 2; mt++)
#pragma unroll
        for (int nt = 0; nt < 4; nt++)
#pragma unroll
            for (int i = 0; i < 4; i++) acc[mt][nt][i] = 0.f;

    {
        cpasync16(sbase + OFF_PHI + (uint32_t)tid * 16, Pb + (uint32_t)tid * 16);
        CP_COMMIT();
    }
    float ra[16];
#pragma unroll
    for (int j = 0; j < 16; j++) ra[j] = aptr[(size_t)j * NN];

    for (int i = 0; i < NCHUNK; i++) {
        const uint32_t bufo = sbase + (uint32_t)(i & 1) * STG_STRIDE;
        {
            uint32_t h[4], l[4];
#pragma unroll
            for (int q = 0; q < 4; q++) splitpairh(ra[2*q], ra[2*q+1], h[q], l[q]);
            sts128(bufo + relA0, h[0], h[1], h[2], h[3]);
            sts128(bufo + OFF_ALO + relA0, l[0], l[1], l[2], l[3]);
#pragma unroll
            for (int q = 0; q < 4; q++) splitpairh(ra[8+2*q], ra[9+2*q], h[q], l[q]);
            sts128(bufo + relA1, h[0], h[1], h[2], h[3]);
            sts128(bufo + OFF_ALO + relA1, l[0], l[1], l[2], l[3]);
        }
        if (i + 1 < NCHUNK) {
            const float* ap = aptr + (size_t)(i + 1) * KC * NN;
#pragma unroll
            for (int j = 0; j < 16; j++) ra[j] = ap[(size_t)j * NN];
        }
        CP_WAIT0();
        __syncthreads();
        if (i + 1 < NCHUNK) {
            const uint32_t nb2 = sbase + (uint32_t)((i + 1) & 1) * STG_STRIDE;
            cpasync16(nb2 + OFF_PHI + (uint32_t)tid * 16,
                      Pb + (size_t)(i + 1) * TILEB + (uint32_t)tid * 16);
            CP_COMMIT();
        }
        // dump split adj tile (16KB) to gmem, coalesced
        {
            unsigned char* dst = Adump + (size_t)i * TILEA;
            const uint32_t t16 = (uint32_t)tid * 16;
#pragma unroll
            for (int q = 0; q < 4; q++) {
                uint4 v = lds128(bufo + t16 + (uint32_t)q * 4096);
                *(uint4*)(dst + t16 + q * 4096) = v;
            }
        }
        // compute: 2 products (Ph*Ah_hi, Ph*Ah_lo)
        const uint32_t AHI = bufo, ALO = bufo + OFF_ALO, PHI = bufo + OFF_PHI;
#pragma unroll
        for (int ks = 0; ks < 2; ks++) {
            const uint32_t kb = lkb + (uint32_t)ks * 32;
            uint32_t ah[2][4], bh[2][4], bl[2][4];
#pragma unroll
            for (int mt = 0; mt < 2; mt++) {
                uint32_t row = (uint32_t)(cb + mt * 16 + lrow);
                uint32_t off = row * 64 + (kb ^ ((row << 3) & 0x30));
                ldsm4(ah[mt], PHI + off);
            }
#pragma unroll
            for (int g = 0; g < 2; g++) {
                uint32_t row = (uint32_t)(nb + g * 16 + lrow);
                uint32_t off = row * 64 + (kb ^ ((row << 3) & 0x30));
                ldsm4(bh[g], AHI + off);
                ldsm4(bl[g], ALO + off);
            }
#pragma unroll
            for (int mt = 0; mt < 2; mt++)
#pragma unroll
                for (int g = 0; g < 2; g++)
#pragma unroll
                    for (int ss = 0; ss < 2; ss++)
                        mma16816(acc[mt][g * 2 + ss], ah[mt], bh[g][ss], bh[g][ss + 2]);
#pragma unroll
            for (int mt = 0; mt < 2; mt++)
#pragma unroll
                for (int g = 0; g < 2; g++)
#pragma unroll
                    for (int ss = 0; ss < 2; ss++)
                        mma16816(acc[mt][g * 2 + ss], ah[mt], bl[g][ss], bl[g][ss + 2]);
        }
    }

    // epilogue: write fp16 P tiles (next step's A operand)
    const int r4 = lane >> 2;
    const int c2 = (lane & 3) * 2;
    unsigned char* Sb = Pdst + (size_t)b * NCHUNK * TILEB;
#pragma unroll
    for (int mt = 0; mt < 2; mt++) {
#pragma unroll
        for (int rp = 0; rp < 2; rp++) {
            const int cc = cb + mt * 16 + rp * 8 + r4;
            const float* Zrow = Zad + ((size_t)b * NC + cc) * NN + m0;
            const uint32_t xorc = (uint32_t)((cc << 3) & 0x30);
            const uint32_t rowo = (uint32_t)cc * 64;
#pragma unroll
            for (int nt = 0; nt < 4; nt++) {
                const int mloc = nb + nt * 8 + c2;
                const int gm = m0 + mloc;
                const int kc = gm >> 5, kk = gm & 31;
                float2 z = *(const float2*)(Zrow + mloc);
                float v0 = acc[mt][nt][rp * 2 + 0] + z.x;
                float v1 = acc[mt][nt][rp * 2 + 1] + z.y;
                unsigned char* tile = Sb + (size_t)kc * TILEB;
                const uint32_t off = rowo + (((uint32_t)(kk * 2)) ^ xorc);
                *(uint32_t*)(tile + off) = packh(v0, v1);
            }
        }
    }
}

// ---------------------------------------------------------------------------
// Steps 1/2: pure streaming, 4-stage cp.async ring, 2 MMA products.
// ---------------------------------------------------------------------------
__global__ void __launch_bounds__(256, 2) stream_step_kernel(
    int step, const float* __restrict__ bias1, const float* __restrict__ bias2,
    float* __restrict__ d_out)
{
    const unsigned char* Psrc = (step == 1) ? g_S0 : g_S1;
    unsigned char* Pdst = g_S1;
    const float* Zad = g_Z + (size_t)(2 - step) * NB * NC * NN;

    extern __shared__ char dynsm[];
    const uint32_t sbase = (smem_u32(dynsm) + 1023u) & ~1023u;

    const int tid = threadIdx.x, warp = tid >> 5, lane = tid & 31;
    const int b = blockIdx.y, mt0 = blockIdx.x, m0 = mt0 * MT;
    const unsigned char* Ab = g_AS + ((size_t)(b * 16 + mt0)) * NCHUNK * TILEA;
    const unsigned char* Pb = Psrc + (size_t)b * NCHUNK * TILEB;
    const uint32_t t16 = (uint32_t)tid * 16;

    const int cb = (warp >> 2) * 32;
    const int nb = (warp & 3) * 32;
    const int lrow = lane & 15;
    const uint32_t lkb = (uint32_t)((lane >> 4) * 16);

    float acc[2][4][4];
#pragma unroll
    for (int mt = 0; mt < 2; mt++)
#pragma unroll
        for (int nt = 0; nt < 4; nt++)
#pragma unroll
            for (int i = 0; i < 4; i++) acc[mt][nt][i] = 0.f;

#define ISSUE_STAGE(i) do {                                                    \
    const uint32_t stg_ = sbase + (uint32_t)((i) & 3) * STG_STRIDE;            \
    const unsigned char* as_ = Ab + (size_t)(i) * TILEA;                       \
    const unsigned char* ps_ = Pb + (size_t)(i) * TILEB;                       \
    cpasync16(stg_ + t16,          as_ + t16);                                 \
    cpasync16(stg_ + t16 + 4096,   as_ + t16 + 4096);                          \
    cpasync16(stg_ + t16 + 8192,   as_ + t16 + 8192);                          \
    cpasync16(stg_ + t16 + 12288,  as_ + t16 + 12288);                         \
    cpasync16(stg_ + OFF_PHI + t16, ps_ + t16);                                \
    CP_COMMIT();                                                               \
} while (0)

    ISSUE_STAGE(0); ISSUE_STAGE(1); ISSUE_STAGE(2);

    for (int i = 0; i < NCHUNK; i++) {
        CP_WAIT2();
        __syncthreads();
        if (i + 3 < NCHUNK) ISSUE_STAGE(i + 3); else CP_COMMIT();
        const uint32_t stg = sbase + (uint32_t)(i & 3) * STG_STRIDE;
        const uint32_t AHI = stg, ALO = stg + OFF_ALO, PHI = stg + OFF_PHI;
#pragma unroll
        for (int ks = 0; ks < 2; ks++) {
            const uint32_t kb = lkb + (uint32_t)ks * 32;
            uint32_t ah[2][4], bh[2][4], bl[2][4];
#pragma unroll
            for (int mt = 0; mt < 2; mt++) {
                uint32_t row = (uint32_t)(cb + mt * 16 + lrow);
                uint32_t off = row * 64 + (kb ^ ((row << 3) & 0x30));
                ldsm4(ah[mt], PHI + off);
            }
#pragma unroll
            for (int g = 0; g < 2; g++) {
                uint32_t row = (uint32_t)(nb + g * 16 + lrow);
                uint32_t off = row * 64 + (kb ^ ((row << 3) & 0x30));
                ldsm4(bh[g], AHI + off);
                ldsm4(bl[g], ALO + off);
            }
#pragma unroll
            for (int mt = 0; mt < 2; mt++)
#pragma unroll
                for (int g = 0; g < 2; g++)
#pragma unroll
                    for (int ss = 0; ss < 2; ss++)
                        mma16816(acc[mt][g * 2 + ss], ah[mt], bh[g][ss], bh[g][ss + 2]);
#pragma unroll
            for (int mt = 0; mt < 2; mt++)
#pragma unroll
                for (int g = 0; g < 2; g++)
#pragma unroll
                    for (int ss = 0; ss < 2; ss++)
                        mma16816(acc[mt][g * 2 + ss], ah[mt], bl[g][ss], bl[g][ss + 2]);
        }
    }
#undef ISSUE_STAGE

    const int r4 = lane >> 2;
    const int c2 = (lane & 3) * 2;
    if (step < 2) {
        unsigned char* Sb = Pdst + (size_t)b * NCHUNK * TILEB;
#pragma unroll
        for (int mt = 0; mt < 2; mt++) {
#pragma unroll
            for (int rp = 0; rp < 2; rp++) {
                const int cc = cb + mt * 16 + rp * 8 + r4;
                const float* Zrow = Zad + ((size_t)b * NC + cc) * NN + m0;
                const uint32_t xorc = (uint32_t)((cc << 3) & 0x30);
                const uint32_t rowo = (uint32_t)cc * 64;
#pragma unroll
                for (int nt = 0; nt < 4; nt++) {
                    const int mloc = nb + nt * 8 + c2;
                    const int gm = m0 + mloc;
                    const int kc = gm >> 5, kk = gm & 31;
                    float2 z = *(const float2*)(Zrow + mloc);
                    float v0 = acc[mt][nt][rp * 2 + 0] + z.x;
                    float v1 = acc[mt][nt][rp * 2 + 1] + z.y;
                    unsigned char* tile = Sb + (size_t)kc * TILEB;
                    const uint32_t off = rowo + (((uint32_t)(kk * 2)) ^ xorc);
                    *(uint32_t*)(tile + off) = packh(v0, v1);
                }
            }
        }
    } else {
#pragma unroll
        for (int mt = 0; mt < 2; mt++) {
#pragma unroll
            for (int rp = 0; rp < 2; rp++) {
                const int cc = cb + mt * 16 + rp * 8 + r4;
                const float* Zrow = Zad + ((size_t)b * NC + cc) * NN + m0;
                float* Orow = d_out + ((size_t)b * NC + cc) * NN + m0;
                float bv; bool rl;
                if (cc < 32) { bv = bias1[cc]; rl = false; }
                else         { bv = bias2[cc - 32]; rl = true; }
#pragma unroll
                for (int nt = 0; nt < 4; nt++) {
                    const int m = nb + nt * 8 + c2;
                    float2 z = *(const float2*)(Zrow + m);
                    float v0 = acc[mt][nt][rp * 2 + 0] + z.x + bv;
                    float v1 = acc[mt][nt][rp * 2 + 1] + z.y + bv;
                    if (rl) { v0 = fmaxf(v0, 0.f); v1 = fmaxf(v1, 0.f); }
                    float2 o; o.x = v0; o.y = v1;
                    *(float2*)(Orow + m) = o;
                }
            }
        }
    }
}

// ---------------------------------------------------------------------------
extern "C" void kernel_launch(void* const* d_in, const int* in_sizes, int n_in,
                              void* d_out, int out_size) {
    (void)in_sizes; (void)n_in; (void)out_size;
    const float* adj = (const float*)d_in[0];
    const float* x   = (const float*)d_in[1];
    const float* W1  = (const float*)d_in[2];
    const float* b1  = (const float*)d_in[3];
    const float* W2  = (const float*)d_in[4];
    const float* b2  = (const float*)d_in[5];
    float* out = (float*)d_out;

    const int SMEM0 = 2 * STG_STRIDE + 1024;   // 41984
    const int SMEM1 = 4 * STG_STRIDE + 1024;   // 82944
    cudaFuncSetAttribute(first_step_kernel,
                         cudaFuncAttributeMaxDynamicSharedMemorySize, SMEM0);
    cudaFuncSetAttribute(stream_step_kernel,
                         cudaFuncAttributeMaxDynamicSharedMemorySize, SMEM1);

    dim3 gp(NN / 128, NB, 4);
    proj_kernel<<<gp, 256>>>(x, W1, W2);

    dim3 gs(NN / MT, NB);
    first_step_kernel<<<gs, 256, SMEM0>>>(adj);
    stream_step_kernel<<<gs, 256, SMEM1>>>(1, b1, b2, out);
    stream_step_kernel<<<gs, 256, SMEM1>>>(2, b1, b2, out);
}

// round 13
// speedup vs baseline: 1.2110x; 1.2110x over previous
#include <cuda_runtime.h>
#include <cuda_bf16.h>
#include <cstdint>

typedef unsigned long long ull;

#define NB 16
#define NC 64
#define NN 2048
#define MT 128              // node tile per CTA
#define KC 32               // K chunk
#define NCHUNK (NN / KC)
#define TILEB 8192          // split P tile: 4KB hi + 4KB lo
#define TILEA 16384         // split adj tile: 8KB hi + 8KB lo

// stage layout (bytes): AHI 0..8K, ALO 8..16K, PHI 16..20K, PLO 20..24K
#define STG_STRIDE 24576
#define OFF_ALO 8192
#define OFF_PHI 16384

__device__ __align__(16) unsigned char g_ZS[(size_t)NB * NCHUNK * TILEB]; // Z3 split
__device__ __align__(16) unsigned char g_S0[(size_t)NB * NCHUNK * TILEB]; // P after step0
__device__ __align__(16) unsigned char g_S1[(size_t)NB * NCHUNK * TILEB]; // P after step1
__device__ __align__(16) unsigned char g_AS[(size_t)NB * 16 * NCHUNK * TILEA]; // split adj
__device__ __align__(16) unsigned char g_US[(size_t)4 * 2 * TILEB];       // split U_d

// ---------------------------------------------------------------- helpers ---
__device__ __forceinline__ uint32_t smem_u32(const void* p) {
    uint32_t a;
    asm("{ .reg .u64 t; cvta.to.shared.u64 t, %1; cvt.u32.u64 %0, t; }"
        : "=r"(a) : "l"(p));
    return a;
}
__device__ __forceinline__ void sts128(uint32_t a, uint32_t v0, uint32_t v1,
                                       uint32_t v2, uint32_t v3) {
    asm volatile("st.shared.v4.b32 [%0], {%1, %2, %3, %4};"
                 :: "r"(a), "r"(v0), "r"(v1), "r"(v2), "r"(v3) : "memory");
}
__device__ __forceinline__ uint4 lds128(uint32_t a) {
    uint4 v;
    asm volatile("ld.shared.v4.b32 {%0,%1,%2,%3}, [%4];"
                 : "=r"(v.x), "=r"(v.y), "=r"(v.z), "=r"(v.w) : "r"(a));
    return v;
}
__device__ __forceinline__ void ldsm4(uint32_t* r, uint32_t addr) {
    asm volatile("ldmatrix.sync.aligned.m8n8.x4.shared.b16 {%0,%1,%2,%3}, [%4];"
                 : "=r"(r[0]), "=r"(r[1]), "=r"(r[2]), "=r"(r[3]) : "r"(addr));
}
__device__ __forceinline__ void mma16816(float* d, const uint32_t* a,
                                         uint32_t b0, uint32_t b1) {
    asm volatile(
        "mma.sync.aligned.m16n8k16.row.col.f32.bf16.bf16.f32 "
        "{%0,%1,%2,%3}, {%4,%5,%6,%7}, {%8,%9}, {%0,%1,%2,%3};"
        : "+f"(d[0]), "+f"(d[1]), "+f"(d[2]), "+f"(d[3])
        : "r"(a[0]), "r"(a[1]), "r"(a[2]), "r"(a[3]), "r"(b0), "r"(b1));
}
__device__ __forceinline__ void splitpair(float x, float y, uint32_t& hi, uint32_t& lo) {
    __nv_bfloat162 h = __floats2bfloat162_rn(x, y);
    float2 hf = __bfloat1622float2(h);
    __nv_bfloat162 l = __floats2bfloat162_rn(x - hf.x, y - hf.y);
    hi = *reinterpret_cast<uint32_t*>(&h);
    lo = *reinterpret_cast<uint32_t*>(&l);
}
__device__ __forceinline__ void cpasync16(uint32_t dst, const void* src) {
    asm volatile("cp.async.cg.shared.global [%0], [%1], 16;"
                 :: "r"(dst), "l"(src) : "memory");
}
#define CP_COMMIT() asm volatile("cp.async.commit_group;" ::: "memory")
#define CP_WAIT0()  asm volatile("cp.async.wait_group 0;" ::: "memory")
#define CP_WAIT2()  asm volatile("cp.async.wait_group 2;" ::: "memory")

// shared compute: one K-chunk (A = P/U tiles in PHI/PLO, B = adj/x in AHI/ALO)
__device__ __forceinline__ void compute_chunk(
    float acc[2][4][4], uint32_t stg, int cb, int nb, int lrow, uint32_t lkb)
{
    const uint32_t AHI = stg, ALO = stg + OFF_ALO,
                   PHI = stg + OFF_PHI, PLO = stg + OFF_PHI + 4096;
#pragma unroll
    for (int ks = 0; ks < 2; ks++) {
        const uint32_t kb = lkb + (uint32_t)ks * 32;
        uint32_t ah[2][4], al[2][4], bh[2][4], bl[2][4];
#pragma unroll
        for (int mt = 0; mt < 2; mt++) {
            uint32_t row = (uint32_t)(cb + mt * 16 + lrow);
            uint32_t off = row * 64 + (kb ^ ((row << 3) & 0x30));
            ldsm4(ah[mt], PHI + off);
            ldsm4(al[mt], PLO + off);
        }
#pragma unroll
        for (int g = 0; g < 2; g++) {
            uint32_t row = (uint32_t)(nb + g * 16 + lrow);
            uint32_t off = row * 64 + (kb ^ ((row << 3) & 0x30));
            ldsm4(bh[g], AHI + off);
            ldsm4(bl[g], ALO + off);
        }
#pragma unroll
        for (int mt = 0; mt < 2; mt++)
#pragma unroll
            for (int g = 0; g < 2; g++)
#pragma unroll
                for (int ss = 0; ss < 2; ss++)
                    mma16816(acc[mt][g * 2 + ss], ah[mt], bh[g][ss], bh[g][ss + 2]);
#pragma unroll
        for (int mt = 0; mt < 2; mt++)
#pragma unroll
            for (int g = 0; g < 2; g++)
#pragma unroll
                for (int ss = 0; ss < 2; ss++)
                    mma16816(acc[mt][g * 2 + ss], ah[mt], bl[g][ss], bl[g][ss + 2]);
#pragma unroll
        for (int mt = 0; mt < 2; mt++)
#pragma unroll
            for (int g = 0; g < 2; g++)
#pragma unroll
                for (int ss = 0; ss < 2; ss++)
                    mma16816(acc[mt][g * 2 + ss], al[mt], bh[g][ss], bh[g][ss + 2]);
    }
}

// ----------------------------------------------------------------- FFMA2 ----
__device__ __forceinline__ ull pack2(float lo, float hi) {
    ull r; asm("mov.b64 %0, {%1, %2};" : "=l"(r) : "f"(lo), "f"(hi)); return r;
}
__device__ __forceinline__ void unpack2(ull v, float& lo, float& hi) {
    asm("mov.b64 {%0, %1}, %2;" : "=f"(lo), "=f"(hi) : "l"(v));
}
__device__ __forceinline__ void fma2(ull& d, ull a, ull b) {
    asm("fma.rn.f32x2 %0, %1, %2, %0;" : "+l"(d) : "l"(a), "l"(b));
}

// ---------------------------------------------------------------------------
// Setup: split U_d = [W1[d]; W2[d]] into P-format tiles (2 K-chunks each).
// ---------------------------------------------------------------------------
__global__ void setup_u_kernel(const float* __restrict__ W1,
                               const float* __restrict__ W2)
{
    const int t = threadIdx.x;           // 256 = d*64 + c
    const int d = t >> 6, c = t & 63;
    const float* row = (c < 32) ? &W1[(d * 32 + c) * 64]
                                : &W2[(d * 32 + (c - 32)) * 64];
    const uint32_t xorc = (uint32_t)((c << 3) & 0x30);
    const uint32_t rowo = (uint32_t)c * 64;
#pragma unroll
    for (int kc = 0; kc < 2; kc++) {
        unsigned char* tile = g_US + (size_t)(d * 2 + kc) * TILEB;
#pragma unroll
        for (int kk = 0; kk < 32; kk += 2) {
            uint32_t hi, lo;
            splitpair(row[kc * 32 + kk], row[kc * 32 + kk + 1], hi, lo);
            const uint32_t off = rowo + (((uint32_t)(kk * 2)) ^ xorc);
            *(uint32_t*)(tile + off) = hi;
            *(uint32_t*)(tile + 4096 + off) = lo;
        }
    }
}

// ---------------------------------------------------------------------------
// Projection (Z3 seed only): Z3[b][c][m] = sum_k U3[c][k] x[b][k][m] -> g_ZS
// ---------------------------------------------------------------------------
__global__ __launch_bounds__(256) void proj_kernel(
    const float* __restrict__ x, const float* __restrict__ W1,
    const float* __restrict__ W2)
{
    __shared__ float Ut[64][68];
    __shared__ float xs[64][128];
    const int b = blockIdx.y, m0 = blockIdx.x * 128;
    const int tid = threadIdx.x;

    for (int i = tid; i < 64 * 64; i += 256) {
        int c = i >> 6, k = i & 63;
        Ut[k][c] = (c < 32) ? W1[(3 * 32 + c) * 64 + k]
                            : W2[(3 * 32 + (c - 32)) * 64 + k];
    }
    for (int i = tid; i < 64 * 32; i += 256) {
        int k = i >> 5, j4 = (i & 31) * 4;
        *(float4*)&xs[k][j4] = *(const float4*)&x[((size_t)b * NC + k) * NN + m0 + j4];
    }
    __syncthreads();

    const int cg = (tid >> 5) * 8;
    const int mg = (tid & 31) * 4;
    ull acc[8][2];
#pragma unroll
    for (int c = 0; c < 8; c++) { acc[c][0] = 0ull; acc[c][1] = 0ull; }

#pragma unroll 8
    for (int k = 0; k < 64; k++) {
        float4 bv = *(const float4*)&xs[k][mg];
        ull b01 = pack2(bv.x, bv.y), b23 = pack2(bv.z, bv.w);
        float4 a0 = *(const float4*)&Ut[k][cg];
        float4 a1 = *(const float4*)&Ut[k][cg + 4];
        float av[8] = {a0.x, a0.y, a0.z, a0.w, a1.x, a1.y, a1.z, a1.w};
#pragma unroll
        for (int c = 0; c < 8; c++) {
            ull a2 = pack2(av[c], av[c]);
            fma2(acc[c][0], a2, b01);
            fma2(acc[c][1], a2, b23);
        }
    }
    const int gm = m0 + mg;
    const int kc = gm >> 5, kk = gm & 31;
    unsigned char* tile = g_ZS + ((size_t)(b * NCHUNK + kc)) * TILEB;
#pragma unroll
    for (int c = 0; c < 8; c++) {
        float4 o;
        unpack2(acc[c][0], o.x, o.y);
        unpack2(acc[c][1], o.z, o.w);
        const int cc = cg + c;
        const uint32_t xorc = (uint32_t)((cc << 3) & 0x30);
        const uint32_t rowo = (uint32_t)cc * 64;
        uint32_t hi, lo;
        splitpair(o.x, o.y, hi, lo);
        uint32_t off = rowo + (((uint32_t)(kk * 2)) ^ xorc);
        *(uint32_t*)(tile + off) = hi;
        *(uint32_t*)(tile + 4096 + off) = lo;
        splitpair(o.z, o.w, hi, lo);
        off = rowo + (((uint32_t)((kk + 2) * 2)) ^ xorc);
        *(uint32_t*)(tile + off) = hi;
        *(uint32_t*)(tile + 4096 + off) = lo;
    }
}

// ---------------------------------------------------------------------------
// Step 0: acc = U2@x (preamble), then += Z3@adj (mainloop, LDG transpose +
// dump split-adj tiles to g_AS). Epilogue writes S0 tiles (no Z read).
// ---------------------------------------------------------------------------
__global__ void __launch_bounds__(256, 2) first_step_kernel(
    const float* __restrict__ adj, const float* __restrict__ x)
{
    extern __shared__ char dynsm[];
    const uint32_t sbase = (smem_u32(dynsm) + 1023u) & ~1023u;

    const int tid = threadIdx.x, warp = tid >> 5, lane = tid & 31;
    const int b = blockIdx.y, mt0 = blockIdx.x, m0 = mt0 * MT;
    const float* Jm = adj + (size_t)b * NN * NN + m0;
    const unsigned char* Pb = g_ZS + (size_t)b * NCHUNK * TILEB;
    unsigned char* Adump = g_AS + ((size_t)(b * 16 + mt0)) * NCHUNK * TILEA;

    const int amld = tid & 127;
    const int akb  = (tid >> 7) * 16;
    const float* aptr = Jm + (size_t)akb * NN + amld;
    const uint32_t axor = (uint32_t)((amld << 3) & 0x30);
    const uint32_t relA0 = (uint32_t)(amld * 64) + (((uint32_t)(akb * 2)) ^ axor);
    const uint32_t relA1 = (uint32_t)(amld * 64) + (((uint32_t)(akb * 2 + 16)) ^ axor);

    const int cb = (warp >> 2) * 32;
    const int nb = (warp & 3) * 32;
    const int lrow = lane & 15;
    const uint32_t lkb = (uint32_t)((lane >> 4) * 16);

    float acc[2][4][4];
#pragma unroll
    for (int mt = 0; mt < 2; mt++)
#pragma unroll
        for (int nt = 0; nt < 4; nt++)
#pragma unroll
            for (int i = 0; i < 4; i++) acc[mt][nt][i] = 0.f;

    // ---- preamble: acc = U2 @ x_tile (2 chunks) ----
    {
        const float* xJm = x + (size_t)b * NC * NN + m0;
        const float* xptr = xJm + (size_t)akb * NN + amld;
#pragma unroll
        for (int xc = 0; xc < 2; xc++) {
            const uint32_t stg = sbase + (uint32_t)xc * STG_STRIDE;
            float rx[16];
#pragma unroll
            for (int j = 0; j < 16; j++) rx[j] = xptr[(size_t)(xc * KC + j) * NN];
            uint32_t h[4], l[4];
#pragma unroll
            for (int q = 0; q < 4; q++) splitpair(rx[2*q], rx[2*q+1], h[q], l[q]);
            sts128(stg + relA0, h[0], h[1], h[2], h[3]);
            sts128(stg + OFF_ALO + relA0, l[0], l[1], l[2], l[3]);
#pragma unroll
            for (int q = 0; q < 4; q++) splitpair(rx[8+2*q], rx[9+2*q], h[q], l[q]);
            sts128(stg + relA1, h[0], h[1], h[2], h[3]);
            sts128(stg + OFF_ALO + relA1, l[0], l[1], l[2], l[3]);
            const unsigned char* us = g_US + (size_t)(2 * 2 + xc) * TILEB;
            cpasync16(stg + OFF_PHI + (uint32_t)tid * 16, us + (uint32_t)tid * 16);
            cpasync16(stg + OFF_PHI + 4096u + (uint32_t)tid * 16,
                      us + 4096u + (uint32_t)tid * 16);
        }
        CP_COMMIT(); CP_WAIT0();
        __syncthreads();
        compute_chunk(acc, sbase, cb, nb, lrow, lkb);
        compute_chunk(acc, sbase + STG_STRIDE, cb, nb, lrow, lkb);
        __syncthreads();
    }

    // ---- mainloop: acc += Z3 @ adj ----
    {
        cpasync16(sbase + OFF_PHI + (uint32_t)tid * 16, Pb + (uint32_t)tid * 16);
        cpasync16(sbase + OFF_PHI + 4096u + (uint32_t)tid * 16,
                  Pb + 4096u + (uint32_t)tid * 16);
        CP_COMMIT();
    }
    float ra[16];
#pragma unroll
    for (int j = 0; j < 16; j++) ra[j] = aptr[(size_t)j * NN];

    for (int i = 0; i < NCHUNK; i++) {
        const uint32_t bufo = sbase + (uint32_t)(i & 1) * STG_STRIDE;
        {
            uint32_t h[4], l[4];
#pragma unroll
            for (int q = 0; q < 4; q++) splitpair(ra[2*q], ra[2*q+1], h[q], l[q]);
            sts128(bufo + relA0, h[0], h[1], h[2], h[3]);
            sts128(bufo + OFF_ALO + relA0, l[0], l[1], l[2], l[3]);
#pragma unroll
            for (int q = 0; q < 4; q++) splitpair(ra[8+2*q], ra[9+2*q], h[q], l[q]);
            sts128(bufo + relA1, h[0], h[1], h[2], h[3]);
            sts128(bufo + OFF_ALO + relA1, l[0], l[1], l[2], l[3]);
        }
        if (i + 1 < NCHUNK) {
            const float* ap = aptr + (size_t)(i + 1) * KC * NN;
#pragma unroll
            for (int j = 0; j < 16; j++) ra[j] = ap[(size_t)j * NN];
        }
        CP_WAIT0();
        __syncthreads();
        if (i + 1 < NCHUNK) {
            const uint32_t nb2 = sbase + (uint32_t)((i + 1) & 1) * STG_STRIDE;
            const unsigned char* src = Pb + (size_t)(i + 1) * TILEB;
            cpasync16(nb2 + OFF_PHI + (uint32_t)tid * 16, src + (uint32_t)tid * 16);
            cpasync16(nb2 + OFF_PHI + 4096u + (uint32_t)tid * 16,
                      src + 4096u + (uint32_t)tid * 16);
            CP_COMMIT();
        }
        // dump split adj tile (16KB) to gmem, coalesced
        {
            unsigned char* dst = Adump + (size_t)i * TILEA;
            const uint32_t t16 = (uint32_t)tid * 16;
#pragma unroll
            for (int q = 0; q < 4; q++) {
                uint4 v = lds128(bufo + t16 + (uint32_t)q * 4096);
                *(uint4*)(dst + t16 + q * 4096) = v;
            }
        }
        compute_chunk(acc, bufo, cb, nb, lrow, lkb);
    }

    // ---- epilogue: write S0 tiles ----
    const int r4 = lane >> 2;
    const int c2 = (lane & 3) * 2;
    unsigned char* Sb = g_S0 + (size_t)b * NCHUNK * TILEB;
#pragma unroll
    for (int mt = 0; mt < 2; mt++) {
#pragma unroll
        for (int rp = 0; rp < 2; rp++) {
            const int cc = cb + mt * 16 + rp * 8 + r4;
            const uint32_t xorc = (uint32_t)((cc << 3) & 0x30);
            const uint32_t rowo = (uint32_t)cc * 64;
#pragma unroll
            for (int nt = 0; nt < 4; nt++) {
                const int mloc = nb + nt * 8 + c2;
                const int gm = m0 + mloc;
                const int kc = gm >> 5, kk = gm & 31;
                uint32_t hi, lo;
                splitpair(acc[mt][nt][rp * 2 + 0], acc[mt][nt][rp * 2 + 1], hi, lo);
                unsigned char* tile = Sb + (size_t)kc * TILEB;
                const uint32_t off = rowo + (((uint32_t)(kk * 2)) ^ xorc);
                *(uint32_t*)(tile + off) = hi;
                *(uint32_t*)(tile + 4096 + off) = lo;
            }
        }
    }
}

// ---------------------------------------------------------------------------
// Steps 1/2: acc = U_{2-step}@x (preamble), then += P@adj via pure streaming
// (4-stage cp.async ring over pre-split tiles).
// ---------------------------------------------------------------------------
__global__ void __launch_bounds__(256, 2) stream_step_kernel(
    int step, const float* __restrict__ x,
    const float* __restrict__ bias1, const float* __restrict__ bias2,
    float* __restrict__ d_out)
{
    const unsigned char* Psrc = (step == 1) ? g_S0 : g_S1;
    unsigned char* Pdst = g_S1;

    extern __shared__ char dynsm[];
    const uint32_t sbase = (smem_u32(dynsm) + 1023u) & ~1023u;

    const int tid = threadIdx.x, warp = tid >> 5, lane = tid & 31;
    const int b = blockIdx.y, mt0 = blockIdx.x, m0 = mt0 * MT;
    const unsigned char* Ab = g_AS + ((size_t)(b * 16 + mt0)) * NCHUNK * TILEA;
    const unsigned char* Pb = Psrc + (size_t)b * NCHUNK * TILEB;
    const uint32_t t16 = (uint32_t)tid * 16;

    const int cb = (warp >> 2) * 32;
    const int nb = (warp & 3) * 32;
    const int lrow = lane & 15;
    const uint32_t lkb = (uint32_t)((lane >> 4) * 16);

    float acc[2][4][4];
#pragma unroll
    for (int mt = 0; mt < 2; mt++)
#pragma unroll
        for (int nt = 0; nt < 4; nt++)
#pragma unroll
            for (int i = 0; i < 4; i++) acc[mt][nt][i] = 0.f;

    // ---- preamble: acc = U_{2-step} @ x_tile ----
    {
        const int amld = tid & 127;
        const int akb  = (tid >> 7) * 16;
        const uint32_t axor = (uint32_t)((amld << 3) & 0x30);
        const uint32_t relA0 = (uint32_t)(amld * 64) + (((uint32_t)(akb * 2)) ^ axor);
        const uint32_t relA1 = (uint32_t)(amld * 64) + (((uint32_t)(akb * 2 + 16)) ^ axor);
        const float* xJm = x + (size_t)b * NC * NN + m0;
        const float* xptr = xJm + (size_t)akb * NN + amld;
        const int ud = 2 - step;
#pragma unroll
        for (int xc = 0; xc < 2; xc++) {
            const uint32_t stg = sbase + (uint32_t)xc * STG_STRIDE;
            float rx[16];
#pragma unroll
            for (int j = 0; j < 16; j++) rx[j] = xptr[(size_t)(xc * KC + j) * NN];
            uint32_t h[4], l[4];
#pragma unroll
            for (int q = 0; q < 4; q++) splitpair(rx[2*q], rx[2*q+1], h[q], l[q]);
            sts128(stg + relA0, h[0], h[1], h[2], h[3]);
            sts128(stg + OFF_ALO + relA0, l[0], l[1], l[2], l[3]);
#pragma unroll
            for (int q = 0; q < 4; q++) splitpair(rx[8+2*q], rx[9+2*q], h[q], l[q]);
            sts128(stg + relA1, h[0], h[1], h[2], h[3]);
            sts128(stg + OFF_ALO + relA1, l[0], l[1], l[2], l[3]);
            const unsigned char* us = g_US + (size_t)(ud * 2 + xc) * TILEB;
            cpasync16(stg + OFF_PHI + t16, us + t16);
            cpasync16(stg + OFF_PHI + 4096u + t16, us + 4096u + t16);
        }
        CP_COMMIT(); CP_WAIT0();
        __syncthreads();
        compute_chunk(acc, sbase, cb, nb, lrow, lkb);
        compute_chunk(acc, sbase + STG_STRIDE, cb, nb, lrow, lkb);
        __syncthreads();
    }

#define ISSUE_STAGE(i) do {                                                    \
    const uint32_t stg_ = sbase + (uint32_t)((i) & 3) * STG_STRIDE;            \
    const unsigned char* as_ = Ab + (size_t)(i) * TILEA;                       \
    const unsigned char* ps_ = Pb + (size_t)(i) * TILEB;                       \
    cpasync16(stg_ + t16,          as_ + t16);                                 \
    cpasync16(stg_ + t16 + 4096,   as_ + t16 + 4096);                          \
    cpasync16(stg_ + t16 + 8192,   as_ + t16 + 8192);                          \
    cpasync16(stg_ + t16 + 12288,  as_ + t16 + 12288);                         \
    cpasync16(stg_ + OFF_PHI + t16,        ps_ + t16);                         \
    cpasync16(stg_ + OFF_PHI + t16 + 4096, ps_ + t16 + 4096);                  \
    CP_COMMIT();                                                               \
} while (0)

    ISSUE_STAGE(0); ISSUE_STAGE(1); ISSUE_STAGE(2);

    for (int i = 0; i < NCHUNK; i++) {
        CP_WAIT2();
        __syncthreads();
        if (i + 3 < NCHUNK) ISSUE_STAGE(i + 3); else CP_COMMIT();
        compute_chunk(acc, sbase + (uint32_t)(i & 3) * STG_STRIDE,
                      cb, nb, lrow, lkb);
    }
#undef ISSUE_STAGE

    const int r4 = lane >> 2;
    const int c2 = (lane & 3) * 2;
    if (step < 2) {
        unsigned char* Sb = Pdst + (size_t)b * NCHUNK * TILEB;
#pragma unroll
        for (int mt = 0; mt < 2; mt++) {
#pragma unroll
            for (int rp = 0; rp < 2; rp++) {
                const int cc = cb + mt * 16 + rp * 8 + r4;
                const uint32_t xorc = (uint32_t)((cc << 3) & 0x30);
                const uint32_t rowo = (uint32_t)cc * 64;
#pragma unroll
                for (int nt = 0; nt < 4; nt++) {
                    const int mloc = nb + nt * 8 + c2;
                    const int gm = m0 + mloc;
                    const int kc = gm >> 5, kk = gm & 31;
                    uint32_t hi, lo;
                    splitpair(acc[mt][nt][rp * 2 + 0], acc[mt][nt][rp * 2 + 1], hi, lo);
                    unsigned char* tile = Sb + (size_t)kc * TILEB;
                    const uint32_t off = rowo + (((uint32_t)(kk * 2)) ^ xorc);
                    *(uint32_t*)(tile + off) = hi;
                    *(uint32_t*)(tile + 4096 + off) = lo;
                }
            }
        }
    } else {
#pragma unroll
        for (int mt = 0; mt < 2; mt++) {
#pragma unroll
            for (int rp = 0; rp < 2; rp++) {
                const int cc = cb + mt * 16 + rp * 8 + r4;
                float* Orow = d_out + ((size_t)b * NC + cc) * NN + m0;
                float bv; bool rl;
                if (cc < 32) { bv = bias1[cc]; rl = false; }
                else         { bv = bias2[cc - 32]; rl = true; }
#pragma unroll
                for (int nt = 0; nt < 4; nt++) {
                    const int m = nb + nt * 8 + c2;
                    float v0 = acc[mt][nt][rp * 2 + 0] + bv;
                    float v1 = acc[mt][nt][rp * 2 + 1] + bv;
                    if (rl) { v0 = fmaxf(v0, 0.f); v1 = fmaxf(v1, 0.f); }
                    float2 o; o.x = v0; o.y = v1;
                    *(float2*)(Orow + m) = o;
                }
            }
        }
    }
}

// ---------------------------------------------------------------------------
extern "C" void kernel_launch(void* const* d_in, const int* in_sizes, int n_in,
                              void* d_out, int out_size) {
    (void)in_sizes; (void)n_in; (void)out_size;
    const float* adj = (const float*)d_in[0];
    const float* x   = (const float*)d_in[1];
    const float* W1  = (const float*)d_in[2];
    const float* b1  = (const float*)d_in[3];
    const float* W2  = (const float*)d_in[4];
    const float* b2  = (const float*)d_in[5];
    float* out = (float*)d_out;

    const int SMEM0 = 2 * STG_STRIDE + 1024;   // 50176
    const int SMEM1 = 4 * STG_STRIDE + 1024;   // 99328
    cudaFuncSetAttribute(first_step_kernel,
                         cudaFuncAttributeMaxDynamicSharedMemorySize, SMEM0);
    cudaFuncSetAttribute(stream_step_kernel,
                         cudaFuncAttributeMaxDynamicSharedMemorySize, SMEM1);

    setup_u_kernel<<<1, 256>>>(W1, W2);
    dim3 gp(NN / 128, NB);
    proj_kernel<<<gp, 256>>>(x, W1, W2);

    dim3 gs(NN / MT, NB);
    first_step_kernel<<<gs, 256, SMEM0>>>(adj, x);
    stream_step_kernel<<<gs, 256, SMEM1>>>(1, x, b1, b2, out);
    stream_step_kernel<<<gs, 256, SMEM1>>>(2, x, b1, b2, out);
}